// round 1
// baseline (speedup 1.0000x reference)
#include <cuda_runtime.h>
#include <math.h>

#define NB    2
#define NL    1024
#define NV    8
#define NDVP  128
#define NDQ   1024
#define NDSRC 512
#define NW    4
#define NK    8

// Scratch (device globals: no allocation allowed)
__device__ float g_q[NB * NL * NV * NDVP];          // 8 MB  [ (b,l) x (v,k) ]
__device__ float g_k[NB * NL * NV * NDVP];          // 8 MB
__device__ float g_score[NB * NV * NL * NL];        // 64 MB [b,v,q,kq]

// ---------------------------------------------------------------------------
// Tiled fp32 NT GEMM: C[M,N] = A[M,K] * B[N,K]^T (+ bias[N])
// 128x128 tile, BK=16, 256 threads, 8x8 per thread, double-buffered smem.
// ---------------------------------------------------------------------------
__device__ __forceinline__ void gemm_nt_128x128(
    const float* __restrict__ A, int lda,
    const float* __restrict__ B, int ldb,
    float* __restrict__ C, int ldc,
    const float* __restrict__ bias,
    int K)
{
    __shared__ float As[2][16][132];
    __shared__ float Bs[2][16][132];

    const int tid = threadIdx.x;
    const int tx = tid & 15;          // 0..15 -> 8 cols each
    const int ty = tid >> 4;          // 0..15 -> 8 rows each
    const int m0 = blockIdx.y * 128;
    const int n0 = blockIdx.x * 128;

    // global loader: 512 float4 per tile-stage, 2 per thread
    const int ar0 = tid >> 2;               // 0..63
    const int ar1 = ar0 + 64;               // 64..127
    const int ac  = (tid & 3) << 2;         // 0,4,8,12

    const float* Ag = A + (size_t)m0 * lda;
    const float* Bg = B + (size_t)n0 * ldb;

    float acc[8][8];
    #pragma unroll
    for (int i = 0; i < 8; i++)
        #pragma unroll
        for (int j = 0; j < 8; j++) acc[i][j] = 0.f;

    const int nstages = K >> 4;

    // preload stage 0
    float4 pa0 = *(const float4*)(Ag + (size_t)ar0 * lda + ac);
    float4 pa1 = *(const float4*)(Ag + (size_t)ar1 * lda + ac);
    float4 pb0 = *(const float4*)(Bg + (size_t)ar0 * ldb + ac);
    float4 pb1 = *(const float4*)(Bg + (size_t)ar1 * ldb + ac);

    As[0][ac + 0][ar0] = pa0.x; As[0][ac + 1][ar0] = pa0.y;
    As[0][ac + 2][ar0] = pa0.z; As[0][ac + 3][ar0] = pa0.w;
    As[0][ac + 0][ar1] = pa1.x; As[0][ac + 1][ar1] = pa1.y;
    As[0][ac + 2][ar1] = pa1.z; As[0][ac + 3][ar1] = pa1.w;
    Bs[0][ac + 0][ar0] = pb0.x; Bs[0][ac + 1][ar0] = pb0.y;
    Bs[0][ac + 2][ar0] = pb0.z; Bs[0][ac + 3][ar0] = pb0.w;
    Bs[0][ac + 0][ar1] = pb1.x; Bs[0][ac + 1][ar1] = pb1.y;
    Bs[0][ac + 2][ar1] = pb1.z; Bs[0][ac + 3][ar1] = pb1.w;
    __syncthreads();

    for (int t = 0; t < nstages; ++t) {
        const int cur = t & 1;
        if (t + 1 < nstages) {
            const int k0 = (t + 1) << 4;
            pa0 = *(const float4*)(Ag + (size_t)ar0 * lda + k0 + ac);
            pa1 = *(const float4*)(Ag + (size_t)ar1 * lda + k0 + ac);
            pb0 = *(const float4*)(Bg + (size_t)ar0 * ldb + k0 + ac);
            pb1 = *(const float4*)(Bg + (size_t)ar1 * ldb + k0 + ac);
        }
        #pragma unroll
        for (int kk = 0; kk < 16; ++kk) {
            float a[8], bf[8];
            *(float4*)&a[0]  = *(const float4*)&As[cur][kk][ty * 8];
            *(float4*)&a[4]  = *(const float4*)&As[cur][kk][ty * 8 + 4];
            *(float4*)&bf[0] = *(const float4*)&Bs[cur][kk][tx * 8];
            *(float4*)&bf[4] = *(const float4*)&Bs[cur][kk][tx * 8 + 4];
            #pragma unroll
            for (int i = 0; i < 8; i++)
                #pragma unroll
                for (int j = 0; j < 8; j++)
                    acc[i][j] += a[i] * bf[j];
        }
        if (t + 1 < nstages) {
            const int nxt = cur ^ 1;
            As[nxt][ac + 0][ar0] = pa0.x; As[nxt][ac + 1][ar0] = pa0.y;
            As[nxt][ac + 2][ar0] = pa0.z; As[nxt][ac + 3][ar0] = pa0.w;
            As[nxt][ac + 0][ar1] = pa1.x; As[nxt][ac + 1][ar1] = pa1.y;
            As[nxt][ac + 2][ar1] = pa1.z; As[nxt][ac + 3][ar1] = pa1.w;
            Bs[nxt][ac + 0][ar0] = pb0.x; Bs[nxt][ac + 1][ar0] = pb0.y;
            Bs[nxt][ac + 2][ar0] = pb0.z; Bs[nxt][ac + 3][ar0] = pb0.w;
            Bs[nxt][ac + 0][ar1] = pb1.x; Bs[nxt][ac + 1][ar1] = pb1.y;
            Bs[nxt][ac + 2][ar1] = pb1.z; Bs[nxt][ac + 3][ar1] = pb1.w;
            __syncthreads();
        }
    }

    // epilogue
    float bb[8];
    #pragma unroll
    for (int j = 0; j < 8; j++)
        bb[j] = bias ? bias[n0 + tx * 8 + j] : 0.f;

    #pragma unroll
    for (int i = 0; i < 8; i++) {
        float* Cr = C + (size_t)(m0 + ty * 8 + i) * ldc + (n0 + tx * 8);
        float4 o0 = make_float4(acc[i][0] + bb[0], acc[i][1] + bb[1],
                                acc[i][2] + bb[2], acc[i][3] + bb[3]);
        float4 o1 = make_float4(acc[i][4] + bb[4], acc[i][5] + bb[5],
                                acc[i][6] + bb[6], acc[i][7] + bb[7]);
        *(float4*)Cr       = o0;
        *(float4*)(Cr + 4) = o1;
    }
}

// ---------------------------------------------------------------------------
// Kernel 1: q/k projections (z=0 -> q, z=1 -> k). grid (8, 16, 2)
// ---------------------------------------------------------------------------
__global__ void __launch_bounds__(256, 2) proj_kernel(
    const float* __restrict__ query, const float* __restrict__ key_t,
    const float* __restrict__ wq, const float* __restrict__ bq,
    const float* __restrict__ wk, const float* __restrict__ bk)
{
    if (blockIdx.z == 0)
        gemm_nt_128x128(query, NDQ, wq, NDQ, g_q, NV * NDVP, bq, NDQ);
    else
        gemm_nt_128x128(key_t, NDQ, wk, NDQ, g_k, NV * NDVP, bk, NDQ);
}

// ---------------------------------------------------------------------------
// Kernel 2: score[b,v] = q[b,v] * k[b,v]^T, 16 batches. grid (8, 8, 16)
// ---------------------------------------------------------------------------
__global__ void __launch_bounds__(256, 2) score_kernel()
{
    const int z = blockIdx.z;
    const int b = z >> 3, v = z & 7;
    const float* A  = g_q + b * (NL * NV * NDVP) + v * NDVP;
    const float* Bm = g_k + b * (NL * NV * NDVP) + v * NDVP;
    float* C = g_score + z * (NL * NL);
    gemm_nt_128x128(A, NV * NDVP, Bm, NV * NDVP, C, NL, nullptr, NDVP);
}

// ---------------------------------------------------------------------------
// Kernel 3: fused top-8 + softmax + windowed gather + weighted sum.
// grid (1024, 8, 2), 256 threads. Warp 0 does top-k; all threads emit output.
// ---------------------------------------------------------------------------
__global__ void __launch_bounds__(256) topk_out_kernel(
    const float* __restrict__ source, float* __restrict__ out)
{
    const int q = blockIdx.x, v = blockIdx.y, b = blockIdx.z;
    const int tid = threadIdx.x;

    __shared__ float s_w[NK];
    __shared__ int   s_idx[NK];

    if (tid < 32) {
        const int lane = tid;
        const float* row = g_score + ((b * NV + v) * NL + q) * NL;

        float best[NK];
        int   bidx[NK];
        #pragma unroll
        for (int j = 0; j < NK; j++) { best[j] = -INFINITY; bidx[j] = 0x7fffffff; }

        // local sorted top-8 over 32 strided (coalesced) values
        for (int i = 0; i < 32; i++) {
            const int idx = i * 32 + lane;
            const float val = row[idx];
            if (val > best[NK - 1]) {
                best[NK - 1] = val; bidx[NK - 1] = idx;
                #pragma unroll
                for (int j = NK - 1; j > 0; --j) {
                    if (best[j] > best[j - 1]) {
                        float tv = best[j]; best[j] = best[j - 1]; best[j - 1] = tv;
                        int   ti = bidx[j]; bidx[j] = bidx[j - 1]; bidx[j - 1] = ti;
                    }
                }
            }
        }

        float vals[NK]; int inds[NK];
        #pragma unroll
        for (int r = 0; r < NK; r++) {
            float v0 = best[0]; int i0 = bidx[0];
            #pragma unroll
            for (int off = 16; off > 0; off >>= 1) {
                float ov = __shfl_down_sync(0xffffffffu, v0, off);
                int   oi = __shfl_down_sync(0xffffffffu, i0, off);
                if (ov > v0 || (ov == v0 && oi < i0)) { v0 = ov; i0 = oi; }
            }
            v0 = __shfl_sync(0xffffffffu, v0, 0);
            i0 = __shfl_sync(0xffffffffu, i0, 0);
            vals[r] = v0; inds[r] = i0;
            if (lane == (i0 & 31)) {   // pop winner from owner lane
                #pragma unroll
                for (int j = 0; j < NK - 1; j++) { best[j] = best[j + 1]; bidx[j] = bidx[j + 1]; }
                best[NK - 1] = -INFINITY; bidx[NK - 1] = 0x7fffffff;
            }
        }

        if (lane == 0) {
            const float m = vals[0];           // vals descending
            float e[NK], sum = 0.f;
            #pragma unroll
            for (int r = 0; r < NK; r++) { e[r] = expf(vals[r] - m); sum += e[r]; }
            const float inv = 1.f / sum;
            #pragma unroll
            for (int r = 0; r < NK; r++) { s_w[r] = e[r] * inv; s_idx[r] = inds[r]; }
        }
    }
    __syncthreads();

    float wloc[NK]; int iloc[NK];
    #pragma unroll
    for (int r = 0; r < NK; r++) { wloc[r] = s_w[r]; iloc[r] = s_idx[r]; }

    const float4* src4 = (const float4*)(source + b * (NL * NDSRC));
    float4* out4 = (float4*)out + (size_t)((b * NV + v) * NL + q) * (NW * NDSRC / 4);

    // 512 output float4s: 2 per thread; window row = idx + w - PAD_F (PAD_F=1)
    #pragma unroll
    for (int e2 = 0; e2 < 2; e2++) {
        const int id = tid + e2 * 256;
        const int w = id >> 7;          // 0..3
        const int f = id & 127;         // float4 index along DSRC
        float4 acc = make_float4(0.f, 0.f, 0.f, 0.f);
        #pragma unroll
        for (int r = 0; r < NK; r++) {
            const int rr = iloc[r] + w - 1;
            if ((unsigned)rr < (unsigned)NL) {
                const float4 s = src4[rr * (NDSRC / 4) + f];
                const float wt = wloc[r];
                acc.x += wt * s.x; acc.y += wt * s.y;
                acc.z += wt * s.z; acc.w += wt * s.w;
            }
        }
        out4[id] = acc;
    }
}

// ---------------------------------------------------------------------------
extern "C" void kernel_launch(void* const* d_in, const int* in_sizes, int n_in,
                              void* d_out, int out_size)
{
    const float* query  = (const float*)d_in[0];
    const float* key_t  = (const float*)d_in[1];
    const float* source = (const float*)d_in[2];
    const float* wq     = (const float*)d_in[3];
    const float* bq     = (const float*)d_in[4];
    const float* wk     = (const float*)d_in[5];
    const float* bk     = (const float*)d_in[6];
    float* out = (float*)d_out;

    proj_kernel<<<dim3(8, 16, 2), 256>>>(query, key_t, wq, bq, wk, bk);
    score_kernel<<<dim3(8, 8, 16), 256>>>();
    topk_out_kernel<<<dim3(NL, NV, NB), 256>>>(source, out);
}

// round 2
// speedup vs baseline: 1.5906x; 1.5906x over previous
#include <cuda_runtime.h>
#include <math.h>

#define NB    2
#define NL    1024
#define NV    8
#define NDVP  128
#define NDQ   1024
#define NDSRC 512
#define NW    4
#define NK    8
#define NROWS (NB * NV * NL)   // 16384 score rows

// Scratch (device globals: no allocation allowed)
__device__ float g_q[NB * NL * NV * NDVP];          // 8 MB  [ (b,l) x (v,k) ]
__device__ float g_k[NB * NL * NV * NDVP];          // 8 MB
__device__ float g_score[NB * NV * NL * NL];        // 64 MB [b,v,q,kq]
__device__ float g_wt[NROWS * NK];                  // softmax weights
__device__ int   g_ix[NROWS * NK];                  // top-k indices

// ---------------------------------------------------------------------------
// Tiled fp32 NT GEMM: C[M,N] = A[M,K] * B[N,K]^T (+ bias[N])
// 128x128 tile, BK=16, 256 threads, warp tile 32x64 (lanes 4x8), 8x8/thread.
// ---------------------------------------------------------------------------
__device__ __forceinline__ void gemm_nt_128x128(
    const float* __restrict__ A, int lda,
    const float* __restrict__ B, int ldb,
    float* __restrict__ C, int ldc,
    const float* __restrict__ bias,
    int K)
{
    __shared__ float As[2][16][132];
    __shared__ float Bs[2][16][132];

    const int tid  = threadIdx.x;
    const int warp = tid >> 5;
    const int lane = tid & 31;
    const int wr = warp & 3;         // warp row  (4) -> 32 rows
    const int wc = warp >> 2;        // warp col  (2) -> 64 cols
    const int lr = lane >> 3;        // lane row  (4) -> 8 rows
    const int lc = lane & 7;         // lane col  (8) -> 8 cols
    const int row0 = wr * 32 + lr * 8;
    const int col0 = wc * 64 + lc * 8;

    const int m0 = blockIdx.y * 128;
    const int n0 = blockIdx.x * 128;

    // global loader: 512 float4 per tile-stage, 2 per thread
    const int ar0 = tid >> 2;               // 0..63
    const int ar1 = ar0 + 64;               // 64..127
    const int ac  = (tid & 3) << 2;         // 0,4,8,12

    const float* Ag = A + (size_t)m0 * lda;
    const float* Bg = B + (size_t)n0 * ldb;

    float acc[8][8];
    #pragma unroll
    for (int i = 0; i < 8; i++)
        #pragma unroll
        for (int j = 0; j < 8; j++) acc[i][j] = 0.f;

    const int nstages = K >> 4;

    // preload stage 0
    float4 pa0 = *(const float4*)(Ag + (size_t)ar0 * lda + ac);
    float4 pa1 = *(const float4*)(Ag + (size_t)ar1 * lda + ac);
    float4 pb0 = *(const float4*)(Bg + (size_t)ar0 * ldb + ac);
    float4 pb1 = *(const float4*)(Bg + (size_t)ar1 * ldb + ac);

    As[0][ac + 0][ar0] = pa0.x; As[0][ac + 1][ar0] = pa0.y;
    As[0][ac + 2][ar0] = pa0.z; As[0][ac + 3][ar0] = pa0.w;
    As[0][ac + 0][ar1] = pa1.x; As[0][ac + 1][ar1] = pa1.y;
    As[0][ac + 2][ar1] = pa1.z; As[0][ac + 3][ar1] = pa1.w;
    Bs[0][ac + 0][ar0] = pb0.x; Bs[0][ac + 1][ar0] = pb0.y;
    Bs[0][ac + 2][ar0] = pb0.z; Bs[0][ac + 3][ar0] = pb0.w;
    Bs[0][ac + 0][ar1] = pb1.x; Bs[0][ac + 1][ar1] = pb1.y;
    Bs[0][ac + 2][ar1] = pb1.z; Bs[0][ac + 3][ar1] = pb1.w;
    __syncthreads();

    for (int t = 0; t < nstages; ++t) {
        const int cur = t & 1;
        if (t + 1 < nstages) {
            const int k0 = (t + 1) << 4;
            pa0 = *(const float4*)(Ag + (size_t)ar0 * lda + k0 + ac);
            pa1 = *(const float4*)(Ag + (size_t)ar1 * lda + k0 + ac);
            pb0 = *(const float4*)(Bg + (size_t)ar0 * ldb + k0 + ac);
            pb1 = *(const float4*)(Bg + (size_t)ar1 * ldb + k0 + ac);
        }
        #pragma unroll
        for (int kk = 0; kk < 16; ++kk) {
            float a[8], bf[8];
            *(float4*)&a[0]  = *(const float4*)&As[cur][kk][row0];
            *(float4*)&a[4]  = *(const float4*)&As[cur][kk][row0 + 4];
            *(float4*)&bf[0] = *(const float4*)&Bs[cur][kk][col0];
            *(float4*)&bf[4] = *(const float4*)&Bs[cur][kk][col0 + 4];
            #pragma unroll
            for (int i = 0; i < 8; i++)
                #pragma unroll
                for (int j = 0; j < 8; j++)
                    acc[i][j] += a[i] * bf[j];
        }
        if (t + 1 < nstages) {
            const int nxt = cur ^ 1;
            As[nxt][ac + 0][ar0] = pa0.x; As[nxt][ac + 1][ar0] = pa0.y;
            As[nxt][ac + 2][ar0] = pa0.z; As[nxt][ac + 3][ar0] = pa0.w;
            As[nxt][ac + 0][ar1] = pa1.x; As[nxt][ac + 1][ar1] = pa1.y;
            As[nxt][ac + 2][ar1] = pa1.z; As[nxt][ac + 3][ar1] = pa1.w;
            Bs[nxt][ac + 0][ar0] = pb0.x; Bs[nxt][ac + 1][ar0] = pb0.y;
            Bs[nxt][ac + 2][ar0] = pb0.z; Bs[nxt][ac + 3][ar0] = pb0.w;
            Bs[nxt][ac + 0][ar1] = pb1.x; Bs[nxt][ac + 1][ar1] = pb1.y;
            Bs[nxt][ac + 2][ar1] = pb1.z; Bs[nxt][ac + 3][ar1] = pb1.w;
            __syncthreads();
        }
    }

    // epilogue
    float bb[8];
    #pragma unroll
    for (int j = 0; j < 8; j++)
        bb[j] = bias ? bias[n0 + col0 + j] : 0.f;

    #pragma unroll
    for (int i = 0; i < 8; i++) {
        float* Cr = C + (size_t)(m0 + row0 + i) * ldc + (n0 + col0);
        float4 o0 = make_float4(acc[i][0] + bb[0], acc[i][1] + bb[1],
                                acc[i][2] + bb[2], acc[i][3] + bb[3]);
        float4 o1 = make_float4(acc[i][4] + bb[4], acc[i][5] + bb[5],
                                acc[i][6] + bb[6], acc[i][7] + bb[7]);
        *(float4*)Cr       = o0;
        *(float4*)(Cr + 4) = o1;
    }
}

// ---------------------------------------------------------------------------
// Kernel 1: q/k projections (z=0 -> q, z=1 -> k). grid (8, 16, 2)
// ---------------------------------------------------------------------------
__global__ void __launch_bounds__(256, 2) proj_kernel(
    const float* __restrict__ query, const float* __restrict__ key_t,
    const float* __restrict__ wq, const float* __restrict__ bq,
    const float* __restrict__ wk, const float* __restrict__ bk)
{
    if (blockIdx.z == 0)
        gemm_nt_128x128(query, NDQ, wq, NDQ, g_q, NV * NDVP, bq, NDQ);
    else
        gemm_nt_128x128(key_t, NDQ, wk, NDQ, g_k, NV * NDVP, bk, NDQ);
}

// ---------------------------------------------------------------------------
// Kernel 2: score[b,v] = q[b,v] * k[b,v]^T, 16 batches. grid (8, 8, 16)
// ---------------------------------------------------------------------------
__global__ void __launch_bounds__(256, 2) score_kernel()
{
    const int z = blockIdx.z;
    const int b = z >> 3, v = z & 7;
    const float* A  = g_q + b * (NL * NV * NDVP) + v * NDVP;
    const float* Bm = g_k + b * (NL * NV * NDVP) + v * NDVP;
    float* C = g_score + z * (NL * NL);
    gemm_nt_128x128(A, NV * NDVP, Bm, NV * NDVP, C, NL, nullptr, NDVP);
}

// ---------------------------------------------------------------------------
// Kernel 3: top-8 + softmax per score row. One warp per row.
// grid 2048 x 256 threads (8 warps/block).
// ---------------------------------------------------------------------------
__global__ void __launch_bounds__(256) topk_kernel()
{
    const int rid  = blockIdx.x * 8 + (threadIdx.x >> 5);
    const int lane = threadIdx.x & 31;
    const float* row = g_score + (size_t)rid * NL;

    float best[NK];
    int   bidx[NK];
    #pragma unroll
    for (int j = 0; j < NK; j++) { best[j] = -INFINITY; bidx[j] = 0x7fffffff; }

    // local sorted top-8 over 32 strided (coalesced) values
    #pragma unroll 4
    for (int i = 0; i < 32; i++) {
        const int idx = i * 32 + lane;
        const float val = row[idx];
        if (val > best[NK - 1]) {
            best[NK - 1] = val; bidx[NK - 1] = idx;
            #pragma unroll
            for (int j = NK - 1; j > 0; --j) {
                if (best[j] > best[j - 1]) {
                    float tv = best[j]; best[j] = best[j - 1]; best[j - 1] = tv;
                    int   ti = bidx[j]; bidx[j] = bidx[j - 1]; bidx[j - 1] = ti;
                }
            }
        }
    }

    float vals[NK]; int inds[NK];
    #pragma unroll
    for (int r = 0; r < NK; r++) {
        float v0 = best[0]; int i0 = bidx[0];
        #pragma unroll
        for (int off = 16; off > 0; off >>= 1) {
            float ov = __shfl_down_sync(0xffffffffu, v0, off);
            int   oi = __shfl_down_sync(0xffffffffu, i0, off);
            if (ov > v0 || (ov == v0 && oi < i0)) { v0 = ov; i0 = oi; }
        }
        v0 = __shfl_sync(0xffffffffu, v0, 0);
        i0 = __shfl_sync(0xffffffffu, i0, 0);
        vals[r] = v0; inds[r] = i0;
        if (lane == (i0 & 31)) {   // pop winner from owner lane
            #pragma unroll
            for (int j = 0; j < NK - 1; j++) { best[j] = best[j + 1]; bidx[j] = bidx[j + 1]; }
            best[NK - 1] = -INFINITY; bidx[NK - 1] = 0x7fffffff;
        }
    }

    if (lane == 0) {
        const float m = vals[0];           // vals descending
        float e[NK], sum = 0.f;
        #pragma unroll
        for (int r = 0; r < NK; r++) { e[r] = expf(vals[r] - m); sum += e[r]; }
        const float inv = 1.f / sum;
        #pragma unroll
        for (int r = 0; r < NK; r++) {
            g_wt[rid * NK + r] = e[r] * inv;
            g_ix[rid * NK + r] = inds[r];
        }
    }
}

// ---------------------------------------------------------------------------
// Kernel 4: windowed gather + weighted sum. grid (1024, 8, 2), 256 threads.
// ---------------------------------------------------------------------------
__global__ void __launch_bounds__(256) out_kernel(
    const float* __restrict__ source, float* __restrict__ out)
{
    const int q = blockIdx.x, v = blockIdx.y, b = blockIdx.z;
    const int tid = threadIdx.x;
    const int rid = (b * NV + v) * NL + q;

    float wloc[NK]; int iloc[NK];
    #pragma unroll
    for (int r = 0; r < NK; r++) {
        wloc[r] = __ldg(&g_wt[rid * NK + r]);
        iloc[r] = __ldg(&g_ix[rid * NK + r]);
    }

    const float4* src4 = (const float4*)(source + b * (NL * NDSRC));
    float4* out4 = (float4*)out + (size_t)rid * (NW * NDSRC / 4);

    // 512 output float4s: 2 per thread; window row = idx + w - PAD_F (PAD_F=1)
    #pragma unroll
    for (int e2 = 0; e2 < 2; e2++) {
        const int id = tid + e2 * 256;
        const int w = id >> 7;          // 0..3
        const int f = id & 127;         // float4 index along DSRC
        float4 acc = make_float4(0.f, 0.f, 0.f, 0.f);
        #pragma unroll
        for (int r = 0; r < NK; r++) {
            const int rr = iloc[r] + w - 1;
            if ((unsigned)rr < (unsigned)NL) {
                const float4 s = __ldg(&src4[rr * (NDSRC / 4) + f]);
                const float wt = wloc[r];
                acc.x += wt * s.x; acc.y += wt * s.y;
                acc.z += wt * s.z; acc.w += wt * s.w;
            }
        }
        out4[id] = acc;
    }
}

// ---------------------------------------------------------------------------
extern "C" void kernel_launch(void* const* d_in, const int* in_sizes, int n_in,
                              void* d_out, int out_size)
{
    const float* query  = (const float*)d_in[0];
    const float* key_t  = (const float*)d_in[1];
    const float* source = (const float*)d_in[2];
    const float* wq     = (const float*)d_in[3];
    const float* bq     = (const float*)d_in[4];
    const float* wk     = (const float*)d_in[5];
    const float* bk     = (const float*)d_in[6];
    float* out = (float*)d_out;

    proj_kernel<<<dim3(8, 16, 2), 256>>>(query, key_t, wq, bq, wk, bk);
    score_kernel<<<dim3(8, 8, 16), 256>>>();
    topk_kernel<<<NROWS / 8, 256>>>();
    out_kernel<<<dim3(NL, NV, NB), 256>>>(source, out);
}

// round 4
// speedup vs baseline: 1.6139x; 1.0147x over previous
#include <cuda_runtime.h>
#include <math.h>
#include <stdint.h>

#define NB    2
#define NL    1024
#define NV    8
#define NDVP  128
#define NDQ   1024
#define NDSRC 512
#define NW    4
#define NK    8
#define NROWS (NB * NV * NL)

// ---------------------------------------------------------------------------
// Device-global scratch (k-major operand layouts: [K][M])
// ---------------------------------------------------------------------------
__device__ float g_qh[1024 * 2048],  g_ql[1024 * 2048];   // query split  [k][b*l]
__device__ float g_kh[1024 * 2048],  g_kl[1024 * 2048];   // key_t split  [k][b*l]
__device__ float g_wqh[1024 * 1024], g_wql[1024 * 1024];  // wq split     [k][v*dvp]
__device__ float g_wkh[1024 * 1024], g_wkl[1024 * 1024];  // wk split     [k][v*dvp]
__device__ float g_pqh[1024 * 2048], g_pql[1024 * 2048];  // proj q split [v*dvp][b*l]
__device__ float g_pkh[1024 * 2048], g_pkl[1024 * 2048];  // proj k split [v*dvp][b*l]
__device__ float g_score[16 * 1024 * 1024];               // 64 MB [b,v,q,kq]
__device__ float g_wt[NROWS * NK];
__device__ int   g_ix[NROWS * NK];

// ---------------------------------------------------------------------------
// helpers
// ---------------------------------------------------------------------------
__device__ __forceinline__ float tf32_round(float x) {
    uint32_t u;
    asm("cvt.rna.tf32.f32 %0, %1;" : "=r"(u) : "f"(x));
    return __uint_as_float(u);
}

__device__ __forceinline__ uint32_t smem_u32(const void* p) {
    uint32_t a;
    asm("{ .reg .u64 t; cvta.to.shared.u64 t, %1; cvt.u32.u64 %0, t; }" : "=r"(a) : "l"(p));
    return a;
}

__device__ __forceinline__ void cp16(uint32_t dst, const void* src) {
    asm volatile("cp.async.cg.shared.global [%0], [%1], 16;" :: "r"(dst), "l"(src) : "memory");
}
__device__ __forceinline__ void cp_commit() { asm volatile("cp.async.commit_group;" ::: "memory"); }
__device__ __forceinline__ void cp_wait1()  { asm volatile("cp.async.wait_group 1;" ::: "memory"); }
__device__ __forceinline__ void cp_wait0()  { asm volatile("cp.async.wait_group 0;" ::: "memory"); }

__device__ __forceinline__ void mma_tf32(float* d, const uint32_t* a, const uint32_t* b) {
    asm volatile(
        "mma.sync.aligned.m16n8k8.row.col.f32.tf32.tf32.f32 "
        "{%0,%1,%2,%3}, {%4,%5,%6,%7}, {%8,%9}, {%0,%1,%2,%3};"
        : "+f"(d[0]), "+f"(d[1]), "+f"(d[2]), "+f"(d[3])
        : "r"(a[0]), "r"(a[1]), "r"(a[2]), "r"(a[3]), "r"(b[0]), "r"(b[1]));
}

// ---------------------------------------------------------------------------
// GEMM config: BM=128, BN=128, BK=16, 256 threads, warps 4x2 (32x64 tile)
// Smem tiles are [BK][136] floats (stride 136 -> conflict-free fragments).
// Stage = 4 tiles (Ah, Al, Bh, Bl) = 4*16*136 floats.
// ---------------------------------------------------------------------------
#define SA        136
#define TILE_F    (16 * SA)          // 2176 floats per tile
#define OFF_AH    0
#define OFF_AL    (1 * TILE_F)
#define OFF_BH    (2 * TILE_F)
#define OFF_BL    (3 * TILE_F)
#define STAGE_F   (4 * TILE_F)       // 8704 floats
#define SMEM_BYTES (2 * STAGE_F * 4) // 69632 bytes

__device__ __forceinline__ void load_tile(uint32_t sb, const float* src, int ld) {
    int id = threadIdx.x * 2;
    #pragma unroll
    for (int i = 0; i < 2; i++, id++) {
        const int k = id >> 5, mc = id & 31;          // 32 x 16B chunks per k-row
        cp16(sb + (uint32_t)(k * SA + mc * 4) * 4, src + (size_t)k * ld + mc * 4);
    }
}

__device__ __forceinline__ void load_stage(uint32_t sb,
    const float* Ah, const float* Al, int lda,
    const float* Bh, const float* Bl, int ldb, int k0)
{
    load_tile(sb + OFF_AH * 4, Ah + (size_t)k0 * lda, lda);
    load_tile(sb + OFF_AL * 4, Al + (size_t)k0 * lda, lda);
    load_tile(sb + OFF_BH * 4, Bh + (size_t)k0 * ldb, ldb);
    load_tile(sb + OFF_BL * 4, Bl + (size_t)k0 * ldb, ldb);
    cp_commit();
}

__device__ __forceinline__ void compute_stage(const float* s, int warp_m, int warp_n,
                                              float acc[2][8][4])
{
    const int lane = threadIdx.x & 31;
    const int g = lane >> 2, tg = lane & 3;
    #pragma unroll
    for (int h = 0; h < 2; h++) {
        const int k8 = h * 8;
        uint32_t aH[2][4], aL[2][4], bH[8][2], bL[8][2];
        #pragma unroll
        for (int ma = 0; ma < 2; ma++) {
            const int m = warp_m + ma * 16 + g;
            const int r0 = (k8 + tg) * SA, r1 = (k8 + tg + 4) * SA;
            aH[ma][0] = __float_as_uint(s[OFF_AH + r0 + m]);
            aH[ma][1] = __float_as_uint(s[OFF_AH + r0 + m + 8]);
            aH[ma][2] = __float_as_uint(s[OFF_AH + r1 + m]);
            aH[ma][3] = __float_as_uint(s[OFF_AH + r1 + m + 8]);
            aL[ma][0] = __float_as_uint(s[OFF_AL + r0 + m]);
            aL[ma][1] = __float_as_uint(s[OFF_AL + r0 + m + 8]);
            aL[ma][2] = __float_as_uint(s[OFF_AL + r1 + m]);
            aL[ma][3] = __float_as_uint(s[OFF_AL + r1 + m + 8]);
        }
        #pragma unroll
        for (int nb = 0; nb < 8; nb++) {
            const int n = warp_n + nb * 8 + g;
            const int r0 = (k8 + tg) * SA, r1 = (k8 + tg + 4) * SA;
            bH[nb][0] = __float_as_uint(s[OFF_BH + r0 + n]);
            bH[nb][1] = __float_as_uint(s[OFF_BH + r1 + n]);
            bL[nb][0] = __float_as_uint(s[OFF_BL + r0 + n]);
            bL[nb][1] = __float_as_uint(s[OFF_BL + r1 + n]);
        }
        #pragma unroll
        for (int ma = 0; ma < 2; ma++)
            #pragma unroll
            for (int nb = 0; nb < 8; nb++) {
                mma_tf32(acc[ma][nb], aH[ma], bH[nb]);
                mma_tf32(acc[ma][nb], aH[ma], bL[nb]);
                mma_tf32(acc[ma][nb], aL[ma], bH[nb]);
            }
    }
}

__device__ __forceinline__ void gemm_mainloop(
    const float* Ah, const float* Al, int lda,
    const float* Bh, const float* Bl, int ldb,
    int nstages, float acc[2][8][4], float* smem)
{
    const uint32_t sb = smem_u32(smem);
    const int warp = threadIdx.x >> 5;
    const int warp_m = (warp & 3) * 32, warp_n = (warp >> 2) * 64;

    load_stage(sb, Ah, Al, lda, Bh, Bl, ldb, 0);
    for (int t = 0; t < nstages; ++t) {
        if (t + 1 < nstages) {
            load_stage(sb + ((t + 1) & 1) * STAGE_F * 4, Ah, Al, lda, Bh, Bl, ldb, (t + 1) * 16);
            cp_wait1();
        } else {
            cp_wait0();
        }
        __syncthreads();
        compute_stage(smem + (t & 1) * STAGE_F, warp_m, warp_n, acc);
        __syncthreads();
    }
}

// ---------------------------------------------------------------------------
// Kernel 1: split + transpose. X[R][C] -> Hi/Lo [C][R] (tf32 hi, tf32 lo).
// block (32,8), 32x32 tiles.
// ---------------------------------------------------------------------------
__global__ void __launch_bounds__(256) split_t_kernel(
    const float* __restrict__ X, float* __restrict__ Hi, float* __restrict__ Lo,
    int R, int C)
{
    __shared__ float sh[32][33], sl[32][33];
    const int tx = threadIdx.x, ty = threadIdx.y;
    const int c0 = blockIdx.x * 32, r0 = blockIdx.y * 32;
    #pragma unroll
    for (int j = 0; j < 4; j++) {
        const int r = r0 + ty + j * 8;
        const float v = X[(size_t)r * C + c0 + tx];
        const float h = tf32_round(v);
        sh[ty + j * 8][tx] = h;
        sl[ty + j * 8][tx] = tf32_round(v - h);
    }
    __syncthreads();
    #pragma unroll
    for (int j = 0; j < 4; j++) {
        const int c = c0 + ty + j * 8;
        Hi[(size_t)c * R + r0 + tx] = sh[tx][ty + j * 8];
        Lo[(size_t)c * R + r0 + tx] = sl[tx][ty + j * 8];
    }
}

// ---------------------------------------------------------------------------
// Kernel 2: projections. z=0 -> q, z=1 -> k. grid (8, 16, 2), 256 thr.
// Epilogue: +bias, tf32 split, TRANSPOSED store ([col][row]) for score GEMM.
// ---------------------------------------------------------------------------
__global__ void __launch_bounds__(256, 1) proj_mma_kernel(
    const float* __restrict__ bq, const float* __restrict__ bk)
{
    extern __shared__ float smem[];
    const int z = blockIdx.z;
    const int m0 = blockIdx.y * 128, n0 = blockIdx.x * 128;

    const float* Ah = (z ? g_kh : g_qh) + m0;     // [1024][2048]
    const float* Al = (z ? g_kl : g_ql) + m0;
    const float* Bh = (z ? g_wkh : g_wqh) + n0;   // [1024][1024]
    const float* Bl = (z ? g_wkl : g_wql) + n0;

    float acc[2][8][4];
    #pragma unroll
    for (int i = 0; i < 2; i++)
        #pragma unroll
        for (int j = 0; j < 8; j++)
            #pragma unroll
            for (int r = 0; r < 4; r++) acc[i][j][r] = 0.f;

    gemm_mainloop(Ah, Al, 2048, Bh, Bl, 1024, NDQ / 16, acc, smem);

    const float* bias = z ? bk : bq;
    float* Ho = z ? g_pkh : g_pqh;
    float* Lo_ = z ? g_pkl : g_pql;

    const int warp = threadIdx.x >> 5, lane = threadIdx.x & 31;
    const int warp_m = (warp & 3) * 32, warp_n = (warp >> 2) * 64;
    const int g = lane >> 2, tg = lane & 3;

    #pragma unroll
    for (int ma = 0; ma < 2; ma++)
        #pragma unroll
        for (int nb = 0; nb < 8; nb++) {
            const int row = m0 + warp_m + ma * 16 + g;
            const int col = n0 + warp_n + nb * 8 + 2 * tg;
            #pragma unroll
            for (int rr = 0; rr < 4; rr++) {
                const int r = row + (rr >> 1) * 8;
                const int c = col + (rr & 1);
                const float v = acc[ma][nb][rr] + __ldg(&bias[c]);
                const float h = tf32_round(v);
                Ho[(size_t)c * 2048 + r]  = h;
                Lo_[(size_t)c * 2048 + r] = tf32_round(v - h);
            }
        }
}

// ---------------------------------------------------------------------------
// Kernel 3: score[b,v] = q_v * k_v^T (K=128). grid (8, 8, 16), 256 thr.
// ---------------------------------------------------------------------------
__global__ void __launch_bounds__(256, 1) score_mma_kernel()
{
    extern __shared__ float smem[];
    const int z = blockIdx.z;
    const int b = z >> 3, v = z & 7;
    const int m0 = blockIdx.y * 128, n0 = blockIdx.x * 128;

    const size_t base = (size_t)(v * 128) * 2048 + b * 1024;
    const float* Ah = g_pqh + base + m0;
    const float* Al = g_pql + base + m0;
    const float* Bh = g_pkh + base + n0;
    const float* Bl = g_pkl + base + n0;

    float acc[2][8][4];
    #pragma unroll
    for (int i = 0; i < 2; i++)
        #pragma unroll
        for (int j = 0; j < 8; j++)
            #pragma unroll
            for (int r = 0; r < 4; r++) acc[i][j][r] = 0.f;

    gemm_mainloop(Ah, Al, 2048, Bh, Bl, 2048, NDVP / 16, acc, smem);

    float* C = g_score + ((size_t)z << 20);
    const int warp = threadIdx.x >> 5, lane = threadIdx.x & 31;
    const int warp_m = (warp & 3) * 32, warp_n = (warp >> 2) * 64;
    const int g = lane >> 2, tg = lane & 3;

    #pragma unroll
    for (int ma = 0; ma < 2; ma++)
        #pragma unroll
        for (int nb = 0; nb < 8; nb++) {
            const int row = m0 + warp_m + ma * 16 + g;
            const int col = n0 + warp_n + nb * 8 + 2 * tg;
            *(float2*)&C[(size_t)row * 1024 + col] =
                make_float2(acc[ma][nb][0], acc[ma][nb][1]);
            *(float2*)&C[(size_t)(row + 8) * 1024 + col] =
                make_float2(acc[ma][nb][2], acc[ma][nb][3]);
        }
}

// ---------------------------------------------------------------------------
// Kernel 4: top-8 + softmax per score row. One warp per row.
// ---------------------------------------------------------------------------
__global__ void __launch_bounds__(256) topk_kernel()
{
    const int rid  = blockIdx.x * 8 + (threadIdx.x >> 5);
    const int lane = threadIdx.x & 31;
    const float* row = g_score + (size_t)rid * NL;

    float best[NK];
    int   bidx[NK];
    #pragma unroll
    for (int j = 0; j < NK; j++) { best[j] = -INFINITY; bidx[j] = 0x7fffffff; }

    #pragma unroll 4
    for (int i = 0; i < 32; i++) {
        const int idx = i * 32 + lane;
        const float val = row[idx];
        if (val > best[NK - 1]) {
            best[NK - 1] = val; bidx[NK - 1] = idx;
            #pragma unroll
            for (int j = NK - 1; j > 0; --j) {
                if (best[j] > best[j - 1]) {
                    float tv = best[j]; best[j] = best[j - 1]; best[j - 1] = tv;
                    int   ti = bidx[j]; bidx[j] = bidx[j - 1]; bidx[j - 1] = ti;
                }
            }
        }
    }

    float vals[NK]; int inds[NK];
    #pragma unroll
    for (int r = 0; r < NK; r++) {
        float v0 = best[0]; int i0 = bidx[0];
        #pragma unroll
        for (int off = 16; off > 0; off >>= 1) {
            float ov = __shfl_down_sync(0xffffffffu, v0, off);
            int   oi = __shfl_down_sync(0xffffffffu, i0, off);
            if (ov > v0 || (ov == v0 && oi < i0)) { v0 = ov; i0 = oi; }
        }
        v0 = __shfl_sync(0xffffffffu, v0, 0);
        i0 = __shfl_sync(0xffffffffu, i0, 0);
        vals[r] = v0; inds[r] = i0;
        if (lane == (i0 & 31)) {
            #pragma unroll
            for (int j = 0; j < NK - 1; j++) { best[j] = best[j + 1]; bidx[j] = bidx[j + 1]; }
            best[NK - 1] = -INFINITY; bidx[NK - 1] = 0x7fffffff;
        }
    }

    if (lane == 0) {
        const float m = vals[0];
        float e[NK], sum = 0.f;
        #pragma unroll
        for (int r = 0; r < NK; r++) { e[r] = expf(vals[r] - m); sum += e[r]; }
        const float inv = 1.f / sum;
        #pragma unroll
        for (int r = 0; r < NK; r++) {
            g_wt[rid * NK + r] = e[r] * inv;
            g_ix[rid * NK + r] = inds[r];
        }
    }
}

// ---------------------------------------------------------------------------
// Kernel 5: windowed gather + weighted sum. grid (1024, 8, 2), 256 threads.
// ---------------------------------------------------------------------------
__global__ void __launch_bounds__(256) out_kernel(
    const float* __restrict__ source, float* __restrict__ out)
{
    const int q = blockIdx.x, v = blockIdx.y, b = blockIdx.z;
    const int tid = threadIdx.x;
    const int rid = (b * NV + v) * NL + q;

    float wloc[NK]; int iloc[NK];
    #pragma unroll
    for (int r = 0; r < NK; r++) {
        wloc[r] = __ldg(&g_wt[rid * NK + r]);
        iloc[r] = __ldg(&g_ix[rid * NK + r]);
    }

    const float4* src4 = (const float4*)(source + b * (NL * NDSRC));
    float4* out4 = (float4*)out + (size_t)rid * (NW * NDSRC / 4);

    #pragma unroll
    for (int e2 = 0; e2 < 2; e2++) {
        const int id = tid + e2 * 256;
        const int w = id >> 7;
        const int f = id & 127;
        float4 acc = make_float4(0.f, 0.f, 0.f, 0.f);
        #pragma unroll
        for (int r = 0; r < NK; r++) {
            const int rr = iloc[r] + w - 1;
            if ((unsigned)rr < (unsigned)NL) {
                const float4 s = __ldg(&src4[rr * (NDSRC / 4) + f]);
                const float wt = wloc[r];
                acc.x += wt * s.x; acc.y += wt * s.y;
                acc.z += wt * s.z; acc.w += wt * s.w;
            }
        }
        out4[id] = acc;
    }
}

// ---------------------------------------------------------------------------
extern "C" void kernel_launch(void* const* d_in, const int* in_sizes, int n_in,
                              void* d_out, int out_size)
{
    const float* query  = (const float*)d_in[0];
    const float* key_t  = (const float*)d_in[1];
    const float* source = (const float*)d_in[2];
    const float* wq     = (const float*)d_in[3];
    const float* bq     = (const float*)d_in[4];
    const float* wk     = (const float*)d_in[5];
    const float* bk     = (const float*)d_in[6];
    float* out = (float*)d_out;

    static int inited = 0;
    if (!inited) {
        cudaFuncSetAttribute(proj_mma_kernel,  cudaFuncAttributeMaxDynamicSharedMemorySize, SMEM_BYTES);
        cudaFuncSetAttribute(score_mma_kernel, cudaFuncAttributeMaxDynamicSharedMemorySize, SMEM_BYTES);
        inited = 1;
    }

    void *p_qh, *p_ql, *p_kh, *p_kl, *p_wqh, *p_wql, *p_wkh, *p_wkl;
    cudaGetSymbolAddress(&p_qh,  g_qh);  cudaGetSymbolAddress(&p_ql,  g_ql);
    cudaGetSymbolAddress(&p_kh,  g_kh);  cudaGetSymbolAddress(&p_kl,  g_kl);
    cudaGetSymbolAddress(&p_wqh, g_wqh); cudaGetSymbolAddress(&p_wql, g_wql);
    cudaGetSymbolAddress(&p_wkh, g_wkh); cudaGetSymbolAddress(&p_wkl, g_wkl);

    // 1) split inputs into tf32 hi/lo, transposed to k-major
    split_t_kernel<<<dim3(32, 64), dim3(32, 8)>>>(query, (float*)p_qh, (float*)p_ql, 2048, 1024);
    split_t_kernel<<<dim3(32, 64), dim3(32, 8)>>>(key_t, (float*)p_kh, (float*)p_kl, 2048, 1024);
    split_t_kernel<<<dim3(32, 32), dim3(32, 8)>>>(wq, (float*)p_wqh, (float*)p_wql, 1024, 1024);
    split_t_kernel<<<dim3(32, 32), dim3(32, 8)>>>(wk, (float*)p_wkh, (float*)p_wkl, 1024, 1024);

    // 2) projections (tensor pipe via mma.sync tf32), epilogue re-splits
    proj_mma_kernel<<<dim3(8, 16, 2), 256, SMEM_BYTES>>>(bq, bk);

    // 3) score GEMMs
    score_mma_kernel<<<dim3(8, 8, 16), 256, SMEM_BYTES>>>();

    // 4) top-8 + softmax
    topk_kernel<<<NROWS / 8, 256>>>();

    // 5) gather + weighted sum
    out_kernel<<<dim3(NL, NV, NB), 256>>>(source, out);
}

// round 5
// speedup vs baseline: 1.9565x; 1.2123x over previous
#include <cuda_runtime.h>
#include <math.h>
#include <stdint.h>

#define NB    2
#define NL    1024
#define NV    8
#define NDVP  128
#define NDQ   1024
#define NDSRC 512
#define NW    4
#define NK    8
#define NROWS (NB * NV * NL)

// ---------------------------------------------------------------------------
// Device-global scratch (k-major operand layouts: [K][M])
// ---------------------------------------------------------------------------
__device__ float g_qh[1024 * 2048],  g_ql[1024 * 2048];   // query split  [k][b*l]
__device__ float g_kh[1024 * 2048],  g_kl[1024 * 2048];   // key_t split  [k][b*l]
__device__ float g_wqh[1024 * 1024], g_wql[1024 * 1024];  // wq split     [k][v*dvp]
__device__ float g_wkh[1024 * 1024], g_wkl[1024 * 1024];  // wk split     [k][v*dvp]
__device__ float g_pqh[1024 * 2048], g_pql[1024 * 2048];  // proj q split [v*dvp][b*l]
__device__ float g_pkh[1024 * 2048], g_pkl[1024 * 2048];  // proj k split [v*dvp][b*l]
__device__ float g_score[16 * 1024 * 1024];               // 64 MB [b,v,q,kq]
__device__ float g_wt[NROWS * NK];
__device__ int   g_ix[NROWS * NK];

// ---------------------------------------------------------------------------
// helpers
// ---------------------------------------------------------------------------
__device__ __forceinline__ float tf32_round(float x) {
    uint32_t u;
    asm("cvt.rna.tf32.f32 %0, %1;" : "=r"(u) : "f"(x));
    return __uint_as_float(u);
}

__device__ __forceinline__ uint32_t smem_u32(const void* p) {
    uint32_t a;
    asm("{ .reg .u64 t; cvta.to.shared.u64 t, %1; cvt.u32.u64 %0, t; }" : "=r"(a) : "l"(p));
    return a;
}

__device__ __forceinline__ void cp16(uint32_t dst, const void* src) {
    asm volatile("cp.async.cg.shared.global [%0], [%1], 16;" :: "r"(dst), "l"(src) : "memory");
}
__device__ __forceinline__ void cp_commit() { asm volatile("cp.async.commit_group;" ::: "memory"); }
__device__ __forceinline__ void cp_wait2()  { asm volatile("cp.async.wait_group 2;" ::: "memory"); }
__device__ __forceinline__ void cp_wait0()  { asm volatile("cp.async.wait_group 0;" ::: "memory"); }

__device__ __forceinline__ void mma_tf32(float* d, const uint32_t* a, const uint32_t* b) {
    asm volatile(
        "mma.sync.aligned.m16n8k8.row.col.f32.tf32.tf32.f32 "
        "{%0,%1,%2,%3}, {%4,%5,%6,%7}, {%8,%9}, {%0,%1,%2,%3};"
        : "+f"(d[0]), "+f"(d[1]), "+f"(d[2]), "+f"(d[3])
        : "r"(a[0]), "r"(a[1]), "r"(a[2]), "r"(a[3]), "r"(b[0]), "r"(b[1]));
}

// ---------------------------------------------------------------------------
// GEMM config: BM=128, BN=128, BK=16, 128 threads (4 warps, 2x2),
// warp tile 64x64, 3-stage cp.async pipeline.
// Smem tiles are [BK][136] floats (stride 136 -> conflict-free fragments).
// ---------------------------------------------------------------------------
#define SA        136
#define TILE_F    (16 * SA)          // 2176 floats per tile
#define OFF_AH    0
#define OFF_AL    (1 * TILE_F)
#define OFF_BH    (2 * TILE_F)
#define OFF_BL    (3 * TILE_F)
#define STAGE_F   (4 * TILE_F)       // 8704 floats
#define NSTAGE    3
#define SMEM_BYTES (NSTAGE * STAGE_F * 4)  // 104448 bytes

__device__ __forceinline__ void load_tile(uint32_t sb, const float* src, int ld) {
    #pragma unroll
    for (int i = 0; i < 4; i++) {
        const int id = threadIdx.x + i * 128;       // 512 16B chunks per tile
        const int k = id >> 5, mc = id & 31;
        cp16(sb + (uint32_t)(k * SA + mc * 4) * 4, src + (size_t)k * ld + mc * 4);
    }
}

__device__ __forceinline__ void load_stage(uint32_t sb,
    const float* Ah, const float* Al, int lda,
    const float* Bh, const float* Bl, int ldb, int k0)
{
    load_tile(sb + OFF_AH * 4, Ah + (size_t)k0 * lda, lda);
    load_tile(sb + OFF_AL * 4, Al + (size_t)k0 * lda, lda);
    load_tile(sb + OFF_BH * 4, Bh + (size_t)k0 * ldb, ldb);
    load_tile(sb + OFF_BL * 4, Bl + (size_t)k0 * ldb, ldb);
    cp_commit();
}

__device__ __forceinline__ void compute_stage(const float* s, int warp_m, int warp_n,
                                              float acc[4][8][4])
{
    const int lane = threadIdx.x & 31;
    const int g = lane >> 2, tg = lane & 3;
    #pragma unroll
    for (int h = 0; h < 2; h++) {
        const int k8 = h * 8;
        const int r0 = (k8 + tg) * SA, r1 = (k8 + tg + 4) * SA;
        uint32_t aH[4][4], aL[4][4];
        #pragma unroll
        for (int ma = 0; ma < 4; ma++) {
            const int m = warp_m + ma * 16 + g;
            aH[ma][0] = __float_as_uint(s[OFF_AH + r0 + m]);
            aH[ma][1] = __float_as_uint(s[OFF_AH + r0 + m + 8]);
            aH[ma][2] = __float_as_uint(s[OFF_AH + r1 + m]);
            aH[ma][3] = __float_as_uint(s[OFF_AH + r1 + m + 8]);
            aL[ma][0] = __float_as_uint(s[OFF_AL + r0 + m]);
            aL[ma][1] = __float_as_uint(s[OFF_AL + r0 + m + 8]);
            aL[ma][2] = __float_as_uint(s[OFF_AL + r1 + m]);
            aL[ma][3] = __float_as_uint(s[OFF_AL + r1 + m + 8]);
        }
        #pragma unroll
        for (int nbh = 0; nbh < 2; nbh++) {
            uint32_t bH[4][2], bL[4][2];
            #pragma unroll
            for (int j = 0; j < 4; j++) {
                const int n = warp_n + (nbh * 4 + j) * 8 + g;
                bH[j][0] = __float_as_uint(s[OFF_BH + r0 + n]);
                bH[j][1] = __float_as_uint(s[OFF_BH + r1 + n]);
                bL[j][0] = __float_as_uint(s[OFF_BL + r0 + n]);
                bL[j][1] = __float_as_uint(s[OFF_BL + r1 + n]);
            }
            #pragma unroll
            for (int ma = 0; ma < 4; ma++)
                #pragma unroll
                for (int j = 0; j < 4; j++) {
                    float* d = acc[ma][nbh * 4 + j];
                    mma_tf32(d, aH[ma], bH[j]);
                    mma_tf32(d, aH[ma], bL[j]);
                    mma_tf32(d, aL[ma], bH[j]);
                }
        }
    }
}

__device__ __forceinline__ void gemm_mainloop(
    const float* Ah, const float* Al, int lda,
    const float* Bh, const float* Bl, int ldb,
    int nstages, float acc[4][8][4], float* smem)
{
    const uint32_t sb = smem_u32(smem);
    const int warp = threadIdx.x >> 5;
    const int warp_m = (warp & 1) * 64, warp_n = (warp >> 1) * 64;

    #pragma unroll
    for (int sp = 0; sp < NSTAGE; sp++)
        if (sp < nstages)
            load_stage(sb + sp * STAGE_F * 4, Ah, Al, lda, Bh, Bl, ldb, sp * 16);

    int buf = 0;
    for (int t = 0; t < nstages; ++t) {
        if (t + NSTAGE - 1 < nstages) cp_wait2(); else cp_wait0();
        __syncthreads();
        compute_stage(smem + buf * STAGE_F, warp_m, warp_n, acc);
        __syncthreads();
        if (t + NSTAGE < nstages)
            load_stage(sb + buf * STAGE_F * 4, Ah, Al, lda, Bh, Bl, ldb, (t + NSTAGE) * 16);
        buf = (buf == NSTAGE - 1) ? 0 : buf + 1;
    }
}

// ---------------------------------------------------------------------------
// Kernel 1: split + transpose. X[R][C] -> Hi/Lo [C][R] (tf32 hi, tf32 lo).
// ---------------------------------------------------------------------------
__global__ void __launch_bounds__(256) split_t_kernel(
    const float* __restrict__ X, float* __restrict__ Hi, float* __restrict__ Lo,
    int R, int C)
{
    __shared__ float sh[32][33], sl[32][33];
    const int tx = threadIdx.x, ty = threadIdx.y;
    const int c0 = blockIdx.x * 32, r0 = blockIdx.y * 32;
    #pragma unroll
    for (int j = 0; j < 4; j++) {
        const int r = r0 + ty + j * 8;
        const float v = X[(size_t)r * C + c0 + tx];
        const float h = tf32_round(v);
        sh[ty + j * 8][tx] = h;
        sl[ty + j * 8][tx] = tf32_round(v - h);
    }
    __syncthreads();
    #pragma unroll
    for (int j = 0; j < 4; j++) {
        const int c = c0 + ty + j * 8;
        Hi[(size_t)c * R + r0 + tx] = sh[tx][ty + j * 8];
        Lo[(size_t)c * R + r0 + tx] = sl[tx][ty + j * 8];
    }
}

// ---------------------------------------------------------------------------
// Kernel 2: projections. z=0 -> q, z=1 -> k. grid (8, 16, 2), 128 thr.
// Epilogue: +bias, tf32 split, TRANSPOSED store ([col][row]) for score GEMM.
// ---------------------------------------------------------------------------
__global__ void __launch_bounds__(128, 1) proj_mma_kernel(
    const float* __restrict__ bq, const float* __restrict__ bk)
{
    extern __shared__ float smem[];
    const int z = blockIdx.z;
    const int m0 = blockIdx.y * 128, n0 = blockIdx.x * 128;

    const float* Ah = (z ? g_kh : g_qh) + m0;     // [1024][2048]
    const float* Al = (z ? g_kl : g_ql) + m0;
    const float* Bh = (z ? g_wkh : g_wqh) + n0;   // [1024][1024]
    const float* Bl = (z ? g_wkl : g_wql) + n0;

    float acc[4][8][4];
    #pragma unroll
    for (int i = 0; i < 4; i++)
        #pragma unroll
        for (int j = 0; j < 8; j++)
            #pragma unroll
            for (int r = 0; r < 4; r++) acc[i][j][r] = 0.f;

    gemm_mainloop(Ah, Al, 2048, Bh, Bl, 1024, NDQ / 16, acc, smem);

    const float* bias = z ? bk : bq;
    float* Ho = z ? g_pkh : g_pqh;
    float* Lo_ = z ? g_pkl : g_pql;

    const int warp = threadIdx.x >> 5, lane = threadIdx.x & 31;
    const int warp_m = (warp & 1) * 64, warp_n = (warp >> 1) * 64;
    const int g = lane >> 2, tg = lane & 3;

    #pragma unroll
    for (int ma = 0; ma < 4; ma++)
        #pragma unroll
        for (int nb = 0; nb < 8; nb++) {
            const int row = m0 + warp_m + ma * 16 + g;
            const int col = n0 + warp_n + nb * 8 + 2 * tg;
            #pragma unroll
            for (int rr = 0; rr < 4; rr++) {
                const int r = row + (rr >> 1) * 8;
                const int c = col + (rr & 1);
                const float v = acc[ma][nb][rr] + __ldg(&bias[c]);
                const float h = tf32_round(v);
                Ho[(size_t)c * 2048 + r]  = h;
                Lo_[(size_t)c * 2048 + r] = tf32_round(v - h);
            }
        }
}

// ---------------------------------------------------------------------------
// Kernel 3: score[b,v] = q_v * k_v^T (K=128). grid (8, 8, 16), 128 thr.
// ---------------------------------------------------------------------------
__global__ void __launch_bounds__(128, 1) score_mma_kernel()
{
    extern __shared__ float smem[];
    const int z = blockIdx.z;
    const int b = z >> 3, v = z & 7;
    const int m0 = blockIdx.y * 128, n0 = blockIdx.x * 128;

    const size_t base = (size_t)(v * 128) * 2048 + b * 1024;
    const float* Ah = g_pqh + base + m0;
    const float* Al = g_pql + base + m0;
    const float* Bh = g_pkh + base + n0;
    const float* Bl = g_pkl + base + n0;

    float acc[4][8][4];
    #pragma unroll
    for (int i = 0; i < 4; i++)
        #pragma unroll
        for (int j = 0; j < 8; j++)
            #pragma unroll
            for (int r = 0; r < 4; r++) acc[i][j][r] = 0.f;

    gemm_mainloop(Ah, Al, 2048, Bh, Bl, 2048, NDVP / 16, acc, smem);

    float* C = g_score + ((size_t)z << 20);
    const int warp = threadIdx.x >> 5, lane = threadIdx.x & 31;
    const int warp_m = (warp & 1) * 64, warp_n = (warp >> 1) * 64;
    const int g = lane >> 2, tg = lane & 3;

    #pragma unroll
    for (int ma = 0; ma < 4; ma++)
        #pragma unroll
        for (int nb = 0; nb < 8; nb++) {
            const int row = m0 + warp_m + ma * 16 + g;
            const int col = n0 + warp_n + nb * 8 + 2 * tg;
            *(float2*)&C[(size_t)row * 1024 + col] =
                make_float2(acc[ma][nb][0], acc[ma][nb][1]);
            *(float2*)&C[(size_t)(row + 8) * 1024 + col] =
                make_float2(acc[ma][nb][2], acc[ma][nb][3]);
        }
}

// ---------------------------------------------------------------------------
// Kernel 4: top-8 + softmax per score row. One warp per row.
// ---------------------------------------------------------------------------
__global__ void __launch_bounds__(256) topk_kernel()
{
    const int rid  = blockIdx.x * 8 + (threadIdx.x >> 5);
    const int lane = threadIdx.x & 31;
    const float* row = g_score + (size_t)rid * NL;

    float best[NK];
    int   bidx[NK];
    #pragma unroll
    for (int j = 0; j < NK; j++) { best[j] = -INFINITY; bidx[j] = 0x7fffffff; }

    #pragma unroll 4
    for (int i = 0; i < 32; i++) {
        const int idx = i * 32 + lane;
        const float val = row[idx];
        if (val > best[NK - 1]) {
            best[NK - 1] = val; bidx[NK - 1] = idx;
            #pragma unroll
            for (int j = NK - 1; j > 0; --j) {
                if (best[j] > best[j - 1]) {
                    float tv = best[j]; best[j] = best[j - 1]; best[j - 1] = tv;
                    int   ti = bidx[j]; bidx[j] = bidx[j - 1]; bidx[j - 1] = ti;
                }
            }
        }
    }

    float vals[NK]; int inds[NK];
    #pragma unroll
    for (int r = 0; r < NK; r++) {
        float v0 = best[0]; int i0 = bidx[0];
        #pragma unroll
        for (int off = 16; off > 0; off >>= 1) {
            float ov = __shfl_down_sync(0xffffffffu, v0, off);
            int   oi = __shfl_down_sync(0xffffffffu, i0, off);
            if (ov > v0 || (ov == v0 && oi < i0)) { v0 = ov; i0 = oi; }
        }
        v0 = __shfl_sync(0xffffffffu, v0, 0);
        i0 = __shfl_sync(0xffffffffu, i0, 0);
        vals[r] = v0; inds[r] = i0;
        if (lane == (i0 & 31)) {
            #pragma unroll
            for (int j = 0; j < NK - 1; j++) { best[j] = best[j + 1]; bidx[j] = bidx[j + 1]; }
            best[NK - 1] = -INFINITY; bidx[NK - 1] = 0x7fffffff;
        }
    }

    if (lane == 0) {
        const float m = vals[0];
        float e[NK], sum = 0.f;
        #pragma unroll
        for (int r = 0; r < NK; r++) { e[r] = expf(vals[r] - m); sum += e[r]; }
        const float inv = 1.f / sum;
        #pragma unroll
        for (int r = 0; r < NK; r++) {
            g_wt[rid * NK + r] = e[r] * inv;
            g_ix[rid * NK + r] = inds[r];
        }
    }
}

// ---------------------------------------------------------------------------
// Kernel 5: windowed gather + weighted sum. grid (1024, 8, 2), 256 threads.
// ---------------------------------------------------------------------------
__global__ void __launch_bounds__(256) out_kernel(
    const float* __restrict__ source, float* __restrict__ out)
{
    const int q = blockIdx.x, v = blockIdx.y, b = blockIdx.z;
    const int tid = threadIdx.x;
    const int rid = (b * NV + v) * NL + q;

    float wloc[NK]; int iloc[NK];
    #pragma unroll
    for (int r = 0; r < NK; r++) {
        wloc[r] = __ldg(&g_wt[rid * NK + r]);
        iloc[r] = __ldg(&g_ix[rid * NK + r]);
    }

    const float4* src4 = (const float4*)(source + b * (NL * NDSRC));
    float4* out4 = (float4*)out + (size_t)rid * (NW * NDSRC / 4);

    #pragma unroll
    for (int e2 = 0; e2 < 2; e2++) {
        const int id = tid + e2 * 256;
        const int w = id >> 7;
        const int f = id & 127;
        float4 acc = make_float4(0.f, 0.f, 0.f, 0.f);
        #pragma unroll
        for (int r = 0; r < NK; r++) {
            const int rr = iloc[r] + w - 1;
            if ((unsigned)rr < (unsigned)NL) {
                const float4 s = __ldg(&src4[rr * (NDSRC / 4) + f]);
                const float wt = wloc[r];
                acc.x += wt * s.x; acc.y += wt * s.y;
                acc.z += wt * s.z; acc.w += wt * s.w;
            }
        }
        out4[id] = acc;
    }
}

// ---------------------------------------------------------------------------
extern "C" void kernel_launch(void* const* d_in, const int* in_sizes, int n_in,
                              void* d_out, int out_size)
{
    const float* query  = (const float*)d_in[0];
    const float* key_t  = (const float*)d_in[1];
    const float* source = (const float*)d_in[2];
    const float* wq     = (const float*)d_in[3];
    const float* bq     = (const float*)d_in[4];
    const float* wk     = (const float*)d_in[5];
    const float* bk     = (const float*)d_in[6];
    float* out = (float*)d_out;

    static int inited = 0;
    if (!inited) {
        cudaFuncSetAttribute(proj_mma_kernel,  cudaFuncAttributeMaxDynamicSharedMemorySize, SMEM_BYTES);
        cudaFuncSetAttribute(score_mma_kernel, cudaFuncAttributeMaxDynamicSharedMemorySize, SMEM_BYTES);
        inited = 1;
    }

    void *p_qh, *p_ql, *p_kh, *p_kl, *p_wqh, *p_wql, *p_wkh, *p_wkl;
    cudaGetSymbolAddress(&p_qh,  g_qh);  cudaGetSymbolAddress(&p_ql,  g_ql);
    cudaGetSymbolAddress(&p_kh,  g_kh);  cudaGetSymbolAddress(&p_kl,  g_kl);
    cudaGetSymbolAddress(&p_wqh, g_wqh); cudaGetSymbolAddress(&p_wql, g_wql);
    cudaGetSymbolAddress(&p_wkh, g_wkh); cudaGetSymbolAddress(&p_wkl, g_wkl);

    // 1) split inputs into tf32 hi/lo, transposed to k-major
    split_t_kernel<<<dim3(32, 64), dim3(32, 8)>>>(query, (float*)p_qh, (float*)p_ql, 2048, 1024);
    split_t_kernel<<<dim3(32, 64), dim3(32, 8)>>>(key_t, (float*)p_kh, (float*)p_kl, 2048, 1024);
    split_t_kernel<<<dim3(32, 32), dim3(32, 8)>>>(wq, (float*)p_wqh, (float*)p_wql, 1024, 1024);
    split_t_kernel<<<dim3(32, 32), dim3(32, 8)>>>(wk, (float*)p_wkh, (float*)p_wkl, 1024, 1024);

    // 2) projections (tensor pipe via mma.sync tf32), epilogue re-splits
    proj_mma_kernel<<<dim3(8, 16, 2), 128, SMEM_BYTES>>>(bq, bk);

    // 3) score GEMMs
    score_mma_kernel<<<dim3(8, 8, 16), 128, SMEM_BYTES>>>();

    // 4) top-8 + softmax
    topk_kernel<<<NROWS / 8, 256>>>();

    // 5) gather + weighted sum
    out_kernel<<<dim3(NL, NV, NB), 256>>>(source, out);
}